// round 3
// baseline (speedup 1.0000x reference)
#include <cuda_runtime.h>
#include <math.h>

#define HDIM 512
#define NN2 32
#define LEN 2048
#define MM 1025

typedef unsigned long long u64;

// ---- packed f32x2 helpers (sm_103a) --------------------------------------
__device__ __forceinline__ u64 pk2(float lo, float hi) {
    u64 r; asm("mov.b64 %0,{%1,%2};" : "=l"(r) : "f"(lo), "f"(hi)); return r;
}
__device__ __forceinline__ void upk2(u64 v, float& lo, float& hi) {
    asm("mov.b64 {%0,%1},%2;" : "=f"(lo), "=f"(hi) : "l"(v));
}
__device__ __forceinline__ u64 add2(u64 a, u64 b) {
    u64 r; asm("add.rn.f32x2 %0,%1,%2;" : "=l"(r) : "l"(a), "l"(b)); return r;
}
__device__ __forceinline__ u64 mul2(u64 a, u64 b) {
    u64 r; asm("mul.rn.f32x2 %0,%1,%2;" : "=l"(r) : "l"(a), "l"(b)); return r;
}
__device__ __forceinline__ u64 fma2(u64 a, u64 b, u64 c) {
    u64 r; asm("fma.rn.f32x2 %0,%1,%2,%3;" : "=l"(r) : "l"(a), "l"(b), "l"(c)); return r;
}

// Woodbury + bilinear post-factor for one m (r_ab already include dt)
__device__ __forceinline__ float2 wood(float R0, float I0, float R1, float I1,
                                       float R2, float I2, float R3, float I3,
                                       float t) {
    const float dr = 1.0f + R3, di = I3;
    const float idn = __fdividef(1.0f, dr*dr + di*di);
    const float numr = R1*R2 - I1*I2;
    const float numi = R1*I2 + I1*R2;
    const float cr = (numr*dr + numi*di) * idn;
    const float ci = (numi*dr - numr*di) * idn;
    const float kfr = R0 - cr, kfi = I0 - ci;
    return make_float2(kfr - kfi*t, kfi + kfr*t);   // * (1 + i t)
}

// ---------------------------------------------------------------------------
// Fused kernel: one block per h.
// Phase A: Cauchy + Woodbury spectrum (conj pairs fused into one rational
//          term, 2 m-values per thread in f32x2 lanes) -> shared kfs[1025]
// Phase B: irfft(2048) via real-packing + 1024-pt radix-2 Stockham in shared
// ---------------------------------------------------------------------------
__global__ void __launch_bounds__(512, 2)
fused_kernel(const float* __restrict__ log_dt,
             const float* __restrict__ log_w_real,
             const float* __restrict__ w_imag,
             const float* __restrict__ Bmat,
             const float* __restrict__ Cmat,
             const float* __restrict__ Pmat,
             float* __restrict__ out)
{
    __shared__ ulonglong2 s_cd[NN2];        // (c,c),(d,d)
    __shared__ ulonglong2 s_ab[4][NN2];     // (a,a),(b,b) per v-matrix (dt folded)
    __shared__ float2 kfs[MM + 1];          // half-spectrum
    __shared__ float2 sA[1024];
    __shared__ float2 sB[1024];
    __shared__ float2 tw[512];              // tw[j] = e^{+2*pi*i*j/1024}

    const int h   = blockIdx.x;
    const int tid = threadIdx.x;

    // ---- per-h constants (one warp) + twiddle table (all threads) ----
    { float s, c; sincospif((float)tid * (1.0f/512.0f), &s, &c); tw[tid] = make_float2(c, s); }

    if (tid < NN2) {
        const int n   = tid;
        const int idx = h * NN2 + n;
        const float dt = expf(log_dt[h]);
        const float wr = -expf(log_w_real[idx]) * dt;
        const float wi = w_imag[idx] * dt;
        const float c  = wr*wr + wi*wi;
        const float d  = -4.0f * wr;

        const float Br = Bmat[2*idx], Bi = Bmat[2*idx+1];
        const float Cr = Cmat[2*idx], Ci = Cmat[2*idx+1];
        const float Pr = Pmat[2*idx], Pi = Pmat[2*idx+1];
        float vr[4], vi[4];
        vr[0] = Br*Cr - Bi*Ci;  vi[0] = Br*Ci + Bi*Cr;   // B*C
        vr[1] = Br*Pr + Bi*Pi;  vi[1] = Bi*Pr - Br*Pi;   // B*conj(P)
        vr[2] = Pr*Cr - Pi*Ci;  vi[2] = Pr*Ci + Pi*Cr;   // P*C
        vr[3] = Pr*Pr + Pi*Pi;  vi[3] = 0.0f;            // |P|^2

        s_cd[n] = make_ulonglong2(pk2(c, c), pk2(d, d));
        #pragma unroll
        for (int k = 0; k < 4; k++) {
            const float a =  4.0f * dt * vr[k];
            const float b = -2.0f * dt * (vr[k]*wr + vi[k]*wi);
            s_ab[k][n] = make_ulonglong2(pk2(a, a), pk2(b, b));
        }
    }
    __syncthreads();

    // ================= Phase A: spectrum =================
    // tasks: pass 0 -> (m0,m1) = (2tid, 2tid+1) for all threads
    //        pass 1 -> only tid 0, m = 1024 (Nyquist; t clamped -> asymptotic limit)
    for (int pass = 0; pass < 2; pass++) {
        if (pass == 1 && tid != 0) break;
        int m0, m1;
        if (pass == 0) { m0 = 2*tid; m1 = m0 + 1; } else { m0 = 1024; m1 = 1024; }

        float s0, c0, s1, c1;
        sincospif((float)m0 * (1.0f/2048.0f), &s0, &c0);
        sincospif((float)m1 * (1.0f/2048.0f), &s1, &c1);
        const float t0 = fminf(__fdividef(s0, c0), 1e8f);   // tan(pi m/L)
        const float t1 = fminf(__fdividef(s1, c1), 1e8f);

        const u64 tp  = pk2(t0, t1);
        const u64 tn  = pk2(-t0, -t1);
        const u64 t2n = pk2(-4.0f*t0*t0, -4.0f*t1*t1);

        u64 aR0=0, aR1=0, aR2=0, aR3=0;     // Re sums
        u64 aJ0=0, aJ1=0, aJ2=0, aJ3=0;     // -Im sums

        #pragma unroll 4
        for (int n = 0; n < NN2; n++) {
            const ulonglong2 cd = s_cd[n];
            const u64 e   = add2(cd.x, t2n);            // c - 4t^2
            const u64 f   = mul2(cd.y, tp);             // d*t
            const u64 mag = fma2(e, e, mul2(f, f));
            float mlo, mhi; upk2(mag, mlo, mhi);
            const u64 r   = pk2(__fdividef(1.0f, mlo), __fdividef(1.0f, mhi));
            const u64 er  = mul2(e, r);
            const u64 fr  = mul2(f, r);
            const u64 tfr  = mul2(tp, fr);
            const u64 nter = mul2(tn, er);              // -t*e*r
            ulonglong2 ab;
            ab = s_ab[0][n];
            aR0 = fma2(ab.x, tfr,  fma2(ab.y, er, aR0));
            aJ0 = fma2(ab.x, nter, fma2(ab.y, fr, aJ0));
            ab = s_ab[1][n];
            aR1 = fma2(ab.x, tfr,  fma2(ab.y, er, aR1));
            aJ1 = fma2(ab.x, nter, fma2(ab.y, fr, aJ1));
            ab = s_ab[2][n];
            aR2 = fma2(ab.x, tfr,  fma2(ab.y, er, aR2));
            aJ2 = fma2(ab.x, nter, fma2(ab.y, fr, aJ2));
            ab = s_ab[3][n];
            aR3 = fma2(ab.x, tfr,  fma2(ab.y, er, aR3));
            aJ3 = fma2(ab.x, nter, fma2(ab.y, fr, aJ3));
        }

        float R0l,R0h,R1l,R1h,R2l,R2h,R3l,R3h;
        float J0l,J0h,J1l,J1h,J2l,J2h,J3l,J3h;
        upk2(aR0,R0l,R0h); upk2(aR1,R1l,R1h); upk2(aR2,R2l,R2h); upk2(aR3,R3l,R3h);
        upk2(aJ0,J0l,J0h); upk2(aJ1,J1l,J1h); upk2(aJ2,J2l,J2h); upk2(aJ3,J3l,J3h);

        const float2 o0 = wood(R0l,-J0l, R1l,-J1l, R2l,-J2l, R3l,-J3l, t0);
        if (pass == 0) {
            const float2 o1 = wood(R0h,-J0h, R1h,-J1h, R2h,-J2h, R3h,-J3h, t1);
            float4* dst = (float4*)&kfs[2*tid];
            *dst = make_float4(o0.x, o0.y, o1.x, o1.y);
        } else {
            kfs[1024] = o0;
        }
    }
    __syncthreads();

    // ================= Phase B: irfft =================
    // Z'[m] = (E[m] + i*O[m]) / 1024  (real-packing of the c2r transform)
    #pragma unroll
    for (int r = 0; r < 2; r++) {
        const int m = tid + r * 512;
        float2 km = kfs[m];
        float2 kn = kfs[1024 - m];
        if (m == 0) { km.y = 0.f; kn.y = 0.f; }
        const float Ex = 0.5f * (km.x + kn.x);
        const float Ey = 0.5f * (km.y - kn.y);
        const float Ox = 0.5f * (km.x - kn.x);
        const float Oy = 0.5f * (km.y + kn.y);
        float s, c;
        sincospif((float)m * (1.0f / 1024.0f), &s, &c);
        const float Orx = Ox * c - Oy * s;
        const float Ory = Ox * s + Oy * c;
        const float scale = 1.0f / 1024.0f;
        sA[m] = make_float2((Ex - Ory) * scale, (Ey + Orx) * scale);
    }

    // 10 radix-2 Stockham stages (self-sorting), inverse sign (+)
    float2* src = sA;
    float2* dst = sB;
    int s_ = 1, ls = 0;
    for (int ncur = 1024; ncur >= 2; ncur >>= 1) {
        __syncthreads();
        const int mh = ncur >> 1;
        const int q  = tid & (s_ - 1);
        const int p  = tid >> ls;
        const float2 a = src[q + s_ * p];
        const float2 b = src[q + s_ * (p + mh)];
        const float2 sum = make_float2(a.x + b.x, a.y + b.y);
        const float2 dif = make_float2(a.x - b.x, a.y - b.y);
        const float2 w = tw[p << ls];               // e^{+2*pi*i*p/ncur}
        dst[q + s_ * 2 * p]       = sum;
        dst[q + s_ * (2 * p + 1)] = make_float2(dif.x * w.x - dif.y * w.y,
                                                dif.x * w.y + dif.y * w.x);
        float2* t = src; src = dst; dst = t;
        s_ <<= 1; ls++;
    }
    __syncthreads();

    // src == sA after 10 swaps; z[j] = x[2j] + i*x[2j+1]
    float2* o2 = (float2*)(out + (size_t)h * LEN);
    o2[tid]       = src[tid];
    o2[tid + 512] = src[tid + 512];
}

extern "C" void kernel_launch(void* const* d_in, const int* in_sizes, int n_in,
                              void* d_out, int out_size)
{
    const float* log_dt     = (const float*)d_in[0];
    const float* log_w_real = (const float*)d_in[1];
    const float* w_imag     = (const float*)d_in[2];
    const float* Bmat       = (const float*)d_in[3];
    const float* Cmat       = (const float*)d_in[4];
    const float* Pmat       = (const float*)d_in[5];
    float* out = (float*)d_out;

    fused_kernel<<<HDIM, 512>>>(log_dt, log_w_real, w_imag, Bmat, Cmat, Pmat, out);
}

// round 4
// speedup vs baseline: 1.0067x; 1.0067x over previous
#include <cuda_runtime.h>
#include <math.h>

#define HDIM 512
#define NN2 32
#define LEN 2048
#define MM 1025

typedef unsigned long long u64;

// ---- packed f32x2 helpers (sm_103a) --------------------------------------
__device__ __forceinline__ u64 pk2(float lo, float hi) {
    u64 r; asm("mov.b64 %0,{%1,%2};" : "=l"(r) : "f"(lo), "f"(hi)); return r;
}
__device__ __forceinline__ void upk2(u64 v, float& lo, float& hi) {
    asm("mov.b64 {%0,%1},%2;" : "=f"(lo), "=f"(hi) : "l"(v));
}
__device__ __forceinline__ u64 add2(u64 a, u64 b) {
    u64 r; asm("add.rn.f32x2 %0,%1,%2;" : "=l"(r) : "l"(a), "l"(b)); return r;
}
__device__ __forceinline__ u64 mul2(u64 a, u64 b) {
    u64 r; asm("mul.rn.f32x2 %0,%1,%2;" : "=l"(r) : "l"(a), "l"(b)); return r;
}
__device__ __forceinline__ u64 fma2(u64 a, u64 b, u64 c) {
    u64 r; asm("fma.rn.f32x2 %0,%1,%2,%3;" : "=l"(r) : "l"(a), "l"(b), "l"(c)); return r;
}

// Woodbury + bilinear post-factor for one m (r_ab already include dt)
__device__ __forceinline__ float2 wood(float R0, float I0, float R1, float I1,
                                       float R2, float I2, float R3, float I3,
                                       float t) {
    const float dr = 1.0f + R3, di = I3;
    const float idn = __fdividef(1.0f, dr*dr + di*di);
    const float numr = R1*R2 - I1*I2;
    const float numi = R1*I2 + I1*R2;
    const float cr = (numr*dr + numi*di) * idn;
    const float ci = (numi*dr - numr*di) * idn;
    const float kfr = R0 - cr, kfi = I0 - ci;
    return make_float2(kfr - kfi*t, kfi + kfr*t);   // * (1 + i t)
}

// ---------------------------------------------------------------------------
// Fused kernel: one 256-thread block per h, 3 CTAs/SM.
// Phase A: Cauchy + Woodbury spectrum; each thread owns TWO m-pairs
//          (4 m values) as two independent f32x2 accumulation streams.
// Phase B: irfft(2048) via real-packing + 1024-pt radix-2 Stockham.
// ---------------------------------------------------------------------------
__global__ void __launch_bounds__(256, 3)
fused_kernel(const float* __restrict__ log_dt,
             const float* __restrict__ log_w_real,
             const float* __restrict__ w_imag,
             const float* __restrict__ Bmat,
             const float* __restrict__ Cmat,
             const float* __restrict__ Pmat,
             float* __restrict__ out)
{
    __shared__ ulonglong2 s_cd[NN2];        // (c,c),(d,d)
    __shared__ ulonglong2 s_ab[4][NN2];     // (a,a),(b,b) per v-matrix (dt folded)
    __shared__ float2 kfs[MM + 1];          // half-spectrum
    __shared__ float2 sA[1024];
    __shared__ float2 sB[1024];
    __shared__ float2 tw[512];              // tw[j] = e^{+2*pi*i*j/1024}

    const int h   = blockIdx.x;
    const int tid = threadIdx.x;

    // twiddle table (2 entries per thread)
    #pragma unroll
    for (int r = 0; r < 2; r++) {
        const int j = tid + r * 256;
        float s, c; sincospif((float)j * (1.0f/512.0f), &s, &c);
        tw[j] = make_float2(c, s);
    }

    if (tid < NN2) {
        const int n   = tid;
        const int idx = h * NN2 + n;
        const float dt = expf(log_dt[h]);
        const float wr = -expf(log_w_real[idx]) * dt;
        const float wi = w_imag[idx] * dt;
        const float c  = wr*wr + wi*wi;
        const float d  = -4.0f * wr;

        const float Br = Bmat[2*idx], Bi = Bmat[2*idx+1];
        const float Cr = Cmat[2*idx], Ci = Cmat[2*idx+1];
        const float Pr = Pmat[2*idx], Pi = Pmat[2*idx+1];
        float vr[4], vi[4];
        vr[0] = Br*Cr - Bi*Ci;  vi[0] = Br*Ci + Bi*Cr;   // B*C
        vr[1] = Br*Pr + Bi*Pi;  vi[1] = Bi*Pr - Br*Pi;   // B*conj(P)
        vr[2] = Pr*Cr - Pi*Ci;  vi[2] = Pr*Ci + Pi*Cr;   // P*C
        vr[3] = Pr*Pr + Pi*Pi;  vi[3] = 0.0f;            // |P|^2

        s_cd[n] = make_ulonglong2(pk2(c, c), pk2(d, d));
        #pragma unroll
        for (int k = 0; k < 4; k++) {
            const float a =  4.0f * dt * vr[k];
            const float b = -2.0f * dt * (vr[k]*wr + vi[k]*wi);
            s_ab[k][n] = make_ulonglong2(pk2(a, a), pk2(b, b));
        }
    }
    __syncthreads();

    // ================= Phase A: spectrum =================
    // pass 0: all threads, pairs A=(2tid,2tid+1), B=(2(tid+256),2(tid+256)+1)
    // pass 1: tid 0 only, Nyquist m=1024 (t clamped -> asymptotic limit)
    for (int pass = 0; pass < 2; pass++) {
        if (pass == 1 && tid != 0) break;
        int mA, mB;
        if (pass == 0) { mA = 2*tid; mB = 2*(tid + 256); } else { mA = 1024; mB = 1024; }

        float sa0,ca0,sa1,ca1, sb0,cb0,sb1,cb1;
        sincospif((float)mA     * (1.0f/2048.0f), &sa0, &ca0);
        sincospif((float)(mA+1) * (1.0f/2048.0f), &sa1, &ca1);
        sincospif((float)mB     * (1.0f/2048.0f), &sb0, &cb0);
        sincospif((float)(mB+1) * (1.0f/2048.0f), &sb1, &cb1);
        const float tA0 = fminf(__fdividef(sa0, ca0), 1e8f);
        const float tA1 = fminf(__fdividef(sa1, ca1), 1e8f);
        const float tB0 = fminf(__fdividef(sb0, cb0), 1e8f);
        const float tB1 = fminf(__fdividef(sb1, cb1), 1e8f);

        const u64 tpA  = pk2(tA0, tA1),  tpB  = pk2(tB0, tB1);
        const u64 tnA  = pk2(-tA0,-tA1), tnB  = pk2(-tB0,-tB1);
        const u64 t2nA = pk2(-4.0f*tA0*tA0, -4.0f*tA1*tA1);
        const u64 t2nB = pk2(-4.0f*tB0*tB0, -4.0f*tB1*tB1);

        u64 aR0A=0,aR1A=0,aR2A=0,aR3A=0, aJ0A=0,aJ1A=0,aJ2A=0,aJ3A=0;
        u64 aR0B=0,aR1B=0,aR2B=0,aR3B=0, aJ0B=0,aJ1B=0,aJ2B=0,aJ3B=0;

        #pragma unroll 2
        for (int n = 0; n < NN2; n++) {
            const ulonglong2 cd = s_cd[n];
            const ulonglong2 ab0 = s_ab[0][n];
            const ulonglong2 ab1 = s_ab[1][n];
            const ulonglong2 ab2 = s_ab[2][n];
            const ulonglong2 ab3 = s_ab[3][n];

            // ---- stream A ----
            {
                const u64 e   = add2(cd.x, t2nA);
                const u64 f   = mul2(cd.y, tpA);
                const u64 mag = fma2(e, e, mul2(f, f));
                float mlo, mhi; upk2(mag, mlo, mhi);
                const u64 r   = pk2(__fdividef(1.0f, mlo), __fdividef(1.0f, mhi));
                const u64 er  = mul2(e, r);
                const u64 fr  = mul2(f, r);
                const u64 tfr  = mul2(tpA, fr);
                const u64 nter = mul2(tnA, er);
                aR0A = fma2(ab0.x, tfr,  fma2(ab0.y, er, aR0A));
                aJ0A = fma2(ab0.x, nter, fma2(ab0.y, fr, aJ0A));
                aR1A = fma2(ab1.x, tfr,  fma2(ab1.y, er, aR1A));
                aJ1A = fma2(ab1.x, nter, fma2(ab1.y, fr, aJ1A));
                aR2A = fma2(ab2.x, tfr,  fma2(ab2.y, er, aR2A));
                aJ2A = fma2(ab2.x, nter, fma2(ab2.y, fr, aJ2A));
                aR3A = fma2(ab3.x, tfr,  fma2(ab3.y, er, aR3A));
                aJ3A = fma2(ab3.x, nter, fma2(ab3.y, fr, aJ3A));
            }
            // ---- stream B ----
            {
                const u64 e   = add2(cd.x, t2nB);
                const u64 f   = mul2(cd.y, tpB);
                const u64 mag = fma2(e, e, mul2(f, f));
                float mlo, mhi; upk2(mag, mlo, mhi);
                const u64 r   = pk2(__fdividef(1.0f, mlo), __fdividef(1.0f, mhi));
                const u64 er  = mul2(e, r);
                const u64 fr  = mul2(f, r);
                const u64 tfr  = mul2(tpB, fr);
                const u64 nter = mul2(tnB, er);
                aR0B = fma2(ab0.x, tfr,  fma2(ab0.y, er, aR0B));
                aJ0B = fma2(ab0.x, nter, fma2(ab0.y, fr, aJ0B));
                aR1B = fma2(ab1.x, tfr,  fma2(ab1.y, er, aR1B));
                aJ1B = fma2(ab1.x, nter, fma2(ab1.y, fr, aJ1B));
                aR2B = fma2(ab2.x, tfr,  fma2(ab2.y, er, aR2B));
                aJ2B = fma2(ab2.x, nter, fma2(ab2.y, fr, aJ2B));
                aR3B = fma2(ab3.x, tfr,  fma2(ab3.y, er, aR3B));
                aJ3B = fma2(ab3.x, nter, fma2(ab3.y, fr, aJ3B));
            }
        }

        // ---- finalize stream A ----
        {
            float R0l,R0h,R1l,R1h,R2l,R2h,R3l,R3h;
            float J0l,J0h,J1l,J1h,J2l,J2h,J3l,J3h;
            upk2(aR0A,R0l,R0h); upk2(aR1A,R1l,R1h); upk2(aR2A,R2l,R2h); upk2(aR3A,R3l,R3h);
            upk2(aJ0A,J0l,J0h); upk2(aJ1A,J1l,J1h); upk2(aJ2A,J2l,J2h); upk2(aJ3A,J3l,J3h);
            const float2 o0 = wood(R0l,-J0l, R1l,-J1l, R2l,-J2l, R3l,-J3l, tA0);
            if (pass == 0) {
                const float2 o1 = wood(R0h,-J0h, R1h,-J1h, R2h,-J2h, R3h,-J3h, tA1);
                float4* dst = (float4*)&kfs[mA];
                *dst = make_float4(o0.x, o0.y, o1.x, o1.y);
            } else {
                kfs[1024] = o0;
            }
        }
        // ---- finalize stream B (pass 0 only) ----
        if (pass == 0) {
            float R0l,R0h,R1l,R1h,R2l,R2h,R3l,R3h;
            float J0l,J0h,J1l,J1h,J2l,J2h,J3l,J3h;
            upk2(aR0B,R0l,R0h); upk2(aR1B,R1l,R1h); upk2(aR2B,R2l,R2h); upk2(aR3B,R3l,R3h);
            upk2(aJ0B,J0l,J0h); upk2(aJ1B,J1l,J1h); upk2(aJ2B,J2l,J2h); upk2(aJ3B,J3l,J3h);
            const float2 o0 = wood(R0l,-J0l, R1l,-J1l, R2l,-J2l, R3l,-J3l, tB0);
            const float2 o1 = wood(R0h,-J0h, R1h,-J1h, R2h,-J2h, R3h,-J3h, tB1);
            float4* dst = (float4*)&kfs[mB];
            *dst = make_float4(o0.x, o0.y, o1.x, o1.y);
        }
    }
    __syncthreads();

    // ================= Phase B: irfft =================
    // Z'[m] = (E[m] + i*O[m]) / 1024  (real-packing of the c2r transform)
    #pragma unroll
    for (int r = 0; r < 4; r++) {
        const int m = tid + r * 256;
        float2 km = kfs[m];
        float2 kn = kfs[1024 - m];
        if (m == 0) { km.y = 0.f; kn.y = 0.f; }
        const float Ex = 0.5f * (km.x + kn.x);
        const float Ey = 0.5f * (km.y - kn.y);
        const float Ox = 0.5f * (km.x - kn.x);
        const float Oy = 0.5f * (km.y + kn.y);
        float s, c;
        sincospif((float)m * (1.0f / 1024.0f), &s, &c);
        const float Orx = Ox * c - Oy * s;
        const float Ory = Ox * s + Oy * c;
        const float scale = 1.0f / 1024.0f;
        sA[m] = make_float2((Ex - Ory) * scale, (Ey + Orx) * scale);
    }

    // 10 radix-2 Stockham stages (self-sorting), inverse sign (+)
    float2* src = sA;
    float2* dst = sB;
    int s_ = 1, ls = 0;
    for (int ncur = 1024; ncur >= 2; ncur >>= 1) {
        __syncthreads();
        const int mh = ncur >> 1;
        #pragma unroll
        for (int r = 0; r < 2; r++) {
            const int b_ = tid + r * 256;
            const int q  = b_ & (s_ - 1);
            const int p  = b_ >> ls;
            const float2 a = src[q + s_ * p];
            const float2 b = src[q + s_ * (p + mh)];
            const float2 sum = make_float2(a.x + b.x, a.y + b.y);
            const float2 dif = make_float2(a.x - b.x, a.y - b.y);
            const float2 w = tw[p << ls];               // e^{+2*pi*i*p/ncur}
            dst[q + s_ * 2 * p]       = sum;
            dst[q + s_ * (2 * p + 1)] = make_float2(dif.x * w.x - dif.y * w.y,
                                                    dif.x * w.y + dif.y * w.x);
        }
        float2* t = src; src = dst; dst = t;
        s_ <<= 1; ls++;
    }
    __syncthreads();

    // src == sA after 10 swaps; z[j] = x[2j] + i*x[2j+1]
    float2* o2 = (float2*)(out + (size_t)h * LEN);
    #pragma unroll
    for (int r = 0; r < 4; r++)
        o2[tid + r * 256] = src[tid + r * 256];
}

extern "C" void kernel_launch(void* const* d_in, const int* in_sizes, int n_in,
                              void* d_out, int out_size)
{
    const float* log_dt     = (const float*)d_in[0];
    const float* log_w_real = (const float*)d_in[1];
    const float* w_imag     = (const float*)d_in[2];
    const float* Bmat       = (const float*)d_in[3];
    const float* Cmat       = (const float*)d_in[4];
    const float* Pmat       = (const float*)d_in[5];
    float* out = (float*)d_out;

    fused_kernel<<<HDIM, 256>>>(log_dt, log_w_real, w_imag, Bmat, Cmat, Pmat, out);
}

// round 5
// speedup vs baseline: 1.0727x; 1.0656x over previous
#include <cuda_runtime.h>
#include <math.h>

#define HDIM 512
#define NN2 32
#define LEN 2048
#define MM 1025

typedef unsigned long long u64;

// ---- packed f32x2 helpers (sm_103a) --------------------------------------
__device__ __forceinline__ u64 pk2(float lo, float hi) {
    u64 r; asm("mov.b64 %0,{%1,%2};" : "=l"(r) : "f"(lo), "f"(hi)); return r;
}
__device__ __forceinline__ void upk2(u64 v, float& lo, float& hi) {
    asm("mov.b64 {%0,%1},%2;" : "=f"(lo), "=f"(hi) : "l"(v));
}
__device__ __forceinline__ u64 add2(u64 a, u64 b) {
    u64 r; asm("add.rn.f32x2 %0,%1,%2;" : "=l"(r) : "l"(a), "l"(b)); return r;
}
__device__ __forceinline__ u64 mul2(u64 a, u64 b) {
    u64 r; asm("mul.rn.f32x2 %0,%1,%2;" : "=l"(r) : "l"(a), "l"(b)); return r;
}
__device__ __forceinline__ u64 fma2(u64 a, u64 b, u64 c) {
    u64 r; asm("fma.rn.f32x2 %0,%1,%2,%3;" : "=l"(r) : "l"(a), "l"(b), "l"(c)); return r;
}

// Woodbury + bilinear post-factor for one m (r_ab already include dt)
__device__ __forceinline__ float2 wood(float R0, float I0, float R1, float I1,
                                       float R2, float I2, float R3, float I3,
                                       float t) {
    const float dr = 1.0f + R3, di = I3;
    const float idn = __fdividef(1.0f, dr*dr + di*di);
    const float numr = R1*R2 - I1*I2;
    const float numi = R1*I2 + I1*R2;
    const float cr = (numr*dr + numi*di) * idn;
    const float ci = (numi*dr - numr*di) * idn;
    const float kfr = R0 - cr, kfi = I0 - ci;
    return make_float2(kfr - kfi*t, kfi + kfr*t);   // * (1 + i t)
}

// One m-pair (t0, t1) through the full Cauchy + Woodbury chain.
__device__ __forceinline__ void cauchy_pair(
    const ulonglong2* __restrict__ s_cd,
    const ulonglong2 (*__restrict__ s_ab)[NN2],
    float t0, float t1, float2& o0, float2& o1)
{
    const u64 tp  = pk2(t0, t1);
    const u64 tn  = pk2(-t0, -t1);
    const u64 t2n = pk2(-4.0f*t0*t0, -4.0f*t1*t1);

    u64 aR0=0, aR1=0, aR2=0, aR3=0;     // Re sums
    u64 aJ0=0, aJ1=0, aJ2=0, aJ3=0;     // -Im sums

    #pragma unroll 4
    for (int n = 0; n < NN2; n++) {
        const ulonglong2 cd = s_cd[n];
        const u64 e   = add2(cd.x, t2n);            // c - 4t^2
        const u64 f   = mul2(cd.y, tp);             // d*t
        const u64 mag = fma2(e, e, mul2(f, f));
        float mlo, mhi; upk2(mag, mlo, mhi);
        const u64 r   = pk2(__fdividef(1.0f, mlo), __fdividef(1.0f, mhi));
        const u64 er  = mul2(e, r);
        const u64 fr  = mul2(f, r);
        const u64 tfr  = mul2(tp, fr);
        const u64 nter = mul2(tn, er);              // -t*e*r
        ulonglong2 ab;
        ab = s_ab[0][n];
        aR0 = fma2(ab.x, tfr,  fma2(ab.y, er, aR0));
        aJ0 = fma2(ab.x, nter, fma2(ab.y, fr, aJ0));
        ab = s_ab[1][n];
        aR1 = fma2(ab.x, tfr,  fma2(ab.y, er, aR1));
        aJ1 = fma2(ab.x, nter, fma2(ab.y, fr, aJ1));
        ab = s_ab[2][n];
        aR2 = fma2(ab.x, tfr,  fma2(ab.y, er, aR2));
        aJ2 = fma2(ab.x, nter, fma2(ab.y, fr, aJ2));
        ab = s_ab[3][n];
        aR3 = fma2(ab.x, tfr,  fma2(ab.y, er, aR3));
        aJ3 = fma2(ab.x, nter, fma2(ab.y, fr, aJ3));
    }

    float R0l,R0h,R1l,R1h,R2l,R2h,R3l,R3h;
    float J0l,J0h,J1l,J1h,J2l,J2h,J3l,J3h;
    upk2(aR0,R0l,R0h); upk2(aR1,R1l,R1h); upk2(aR2,R2l,R2h); upk2(aR3,R3l,R3h);
    upk2(aJ0,J0l,J0h); upk2(aJ1,J1l,J1h); upk2(aJ2,J2l,J2h); upk2(aJ3,J3l,J3h);

    o0 = wood(R0l,-J0l, R1l,-J1l, R2l,-J2l, R3l,-J3l, t0);
    o1 = wood(R0h,-J0h, R1h,-J1h, R2h,-J2h, R3h,-J3h, t1);
}

// ---------------------------------------------------------------------------
// Fused kernel: one 256-thread block per h, 4 CTAs/SM -> grid 512 fits in a
// SINGLE wave (592 slots). Phase A runs two sequential m-chunks per thread.
// ---------------------------------------------------------------------------
__global__ void __launch_bounds__(256, 4)
fused_kernel(const float* __restrict__ log_dt,
             const float* __restrict__ log_w_real,
             const float* __restrict__ w_imag,
             const float* __restrict__ Bmat,
             const float* __restrict__ Cmat,
             const float* __restrict__ Pmat,
             float* __restrict__ out)
{
    __shared__ ulonglong2 s_cd[NN2];        // (c,c),(d,d)
    __shared__ ulonglong2 s_ab[4][NN2];     // (a,a),(b,b) per v-matrix (dt folded)
    __shared__ float2 kfs[MM + 1];          // half-spectrum
    __shared__ float2 sA[1024];
    __shared__ float2 sB[1024];
    __shared__ float2 tw[512];              // tw[j] = e^{+2*pi*i*j/1024}

    const int h   = blockIdx.x;
    const int tid = threadIdx.x;

    // twiddle table (2 entries per thread)
    #pragma unroll
    for (int r = 0; r < 2; r++) {
        const int j = tid + r * 256;
        float s, c; sincospif((float)j * (1.0f/512.0f), &s, &c);
        tw[j] = make_float2(c, s);
    }

    if (tid < NN2) {
        const int n   = tid;
        const int idx = h * NN2 + n;
        const float dt = expf(log_dt[h]);
        const float wr = -expf(log_w_real[idx]) * dt;
        const float wi = w_imag[idx] * dt;
        const float c  = wr*wr + wi*wi;
        const float d  = -4.0f * wr;

        const float Br = Bmat[2*idx], Bi = Bmat[2*idx+1];
        const float Cr = Cmat[2*idx], Ci = Cmat[2*idx+1];
        const float Pr = Pmat[2*idx], Pi = Pmat[2*idx+1];
        float vr[4], vi[4];
        vr[0] = Br*Cr - Bi*Ci;  vi[0] = Br*Ci + Bi*Cr;   // B*C
        vr[1] = Br*Pr + Bi*Pi;  vi[1] = Bi*Pr - Br*Pi;   // B*conj(P)
        vr[2] = Pr*Cr - Pi*Ci;  vi[2] = Pr*Ci + Pi*Cr;   // P*C
        vr[3] = Pr*Pr + Pi*Pi;  vi[3] = 0.0f;            // |P|^2

        s_cd[n] = make_ulonglong2(pk2(c, c), pk2(d, d));
        #pragma unroll
        for (int k = 0; k < 4; k++) {
            const float a =  4.0f * dt * vr[k];
            const float b = -2.0f * dt * (vr[k]*wr + vi[k]*wi);
            s_ab[k][n] = make_ulonglong2(pk2(a, a), pk2(b, b));
        }
    }
    __syncthreads();

    // ================= Phase A: spectrum =================
    #pragma unroll 1
    for (int pass = 0; pass < 2; pass++) {
        const int m0 = 2 * (tid + 256 * pass);
        float s0, c0, s1, c1;
        sincospif((float)m0       * (1.0f/2048.0f), &s0, &c0);
        sincospif((float)(m0 + 1) * (1.0f/2048.0f), &s1, &c1);
        const float t0 = fminf(__fdividef(s0, c0), 1e8f);   // tan(pi m/L)
        const float t1 = fminf(__fdividef(s1, c1), 1e8f);

        float2 o0, o1;
        cauchy_pair(s_cd, s_ab, t0, t1, o0, o1);
        float4* dst = (float4*)&kfs[m0];
        *dst = make_float4(o0.x, o0.y, o1.x, o1.y);
    }
    // Nyquist m=1024 (t clamped -> converged asymptotic limit)
    if (tid == 0) {
        float2 o0, o1;
        cauchy_pair(s_cd, s_ab, 1e8f, 1e8f, o0, o1);
        kfs[1024] = o0;
    }
    __syncthreads();

    // ================= Phase B: irfft =================
    // Z'[m] = (E[m] + i*O[m]) / 1024  (real-packing of the c2r transform)
    #pragma unroll
    for (int r = 0; r < 4; r++) {
        const int m = tid + r * 256;
        float2 km = kfs[m];
        float2 kn = kfs[1024 - m];
        if (m == 0) { km.y = 0.f; kn.y = 0.f; }
        const float Ex = 0.5f * (km.x + kn.x);
        const float Ey = 0.5f * (km.y - kn.y);
        const float Ox = 0.5f * (km.x - kn.x);
        const float Oy = 0.5f * (km.y + kn.y);
        float s, c;
        sincospif((float)m * (1.0f / 1024.0f), &s, &c);
        const float Orx = Ox * c - Oy * s;
        const float Ory = Ox * s + Oy * c;
        const float scale = 1.0f / 1024.0f;
        sA[m] = make_float2((Ex - Ory) * scale, (Ey + Orx) * scale);
    }

    // 10 radix-2 Stockham stages (self-sorting), inverse sign (+)
    float2* src = sA;
    float2* dst = sB;
    int s_ = 1, ls = 0;
    for (int ncur = 1024; ncur >= 2; ncur >>= 1) {
        __syncthreads();
        const int mh = ncur >> 1;
        #pragma unroll
        for (int r = 0; r < 2; r++) {
            const int b_ = tid + r * 256;
            const int q  = b_ & (s_ - 1);
            const int p  = b_ >> ls;
            const float2 a = src[q + s_ * p];
            const float2 b = src[q + s_ * (p + mh)];
            const float2 sum = make_float2(a.x + b.x, a.y + b.y);
            const float2 dif = make_float2(a.x - b.x, a.y - b.y);
            const float2 w = tw[p << ls];               // e^{+2*pi*i*p/ncur}
            dst[q + s_ * 2 * p]       = sum;
            dst[q + s_ * (2 * p + 1)] = make_float2(dif.x * w.x - dif.y * w.y,
                                                    dif.x * w.y + dif.y * w.x);
        }
        float2* t = src; src = dst; dst = t;
        s_ <<= 1; ls++;
    }
    __syncthreads();

    // src == sA after 10 swaps; z[j] = x[2j] + i*x[2j+1]
    float2* o2 = (float2*)(out + (size_t)h * LEN);
    #pragma unroll
    for (int r = 0; r < 4; r++)
        o2[tid + r * 256] = src[tid + r * 256];
}

extern "C" void kernel_launch(void* const* d_in, const int* in_sizes, int n_in,
                              void* d_out, int out_size)
{
    const float* log_dt     = (const float*)d_in[0];
    const float* log_w_real = (const float*)d_in[1];
    const float* w_imag     = (const float*)d_in[2];
    const float* Bmat       = (const float*)d_in[3];
    const float* Cmat       = (const float*)d_in[4];
    const float* Pmat       = (const float*)d_in[5];
    float* out = (float*)d_out;

    fused_kernel<<<HDIM, 256>>>(log_dt, log_w_real, w_imag, Bmat, Cmat, Pmat, out);
}

// round 6
// speedup vs baseline: 1.0738x; 1.0010x over previous
#include <cuda_runtime.h>
#include <math.h>

#define HDIM 512
#define NN2 32
#define LEN 2048
#define MM 1025

typedef unsigned long long u64;

// ---- packed f32x2 helpers (sm_103a) --------------------------------------
__device__ __forceinline__ u64 pk2(float lo, float hi) {
    u64 r; asm("mov.b64 %0,{%1,%2};" : "=l"(r) : "f"(lo), "f"(hi)); return r;
}
__device__ __forceinline__ void upk2(u64 v, float& lo, float& hi) {
    asm("mov.b64 {%0,%1},%2;" : "=f"(lo), "=f"(hi) : "l"(v));
}
__device__ __forceinline__ u64 add2(u64 a, u64 b) {
    u64 r; asm("add.rn.f32x2 %0,%1,%2;" : "=l"(r) : "l"(a), "l"(b)); return r;
}
__device__ __forceinline__ u64 mul2(u64 a, u64 b) {
    u64 r; asm("mul.rn.f32x2 %0,%1,%2;" : "=l"(r) : "l"(a), "l"(b)); return r;
}
__device__ __forceinline__ u64 fma2(u64 a, u64 b, u64 c) {
    u64 r; asm("fma.rn.f32x2 %0,%1,%2,%3;" : "=l"(r) : "l"(a), "l"(b), "l"(c)); return r;
}

__device__ __forceinline__ float2 cmul(float2 w, float2 y) {
    return make_float2(w.x*y.x - w.y*y.y, w.x*y.y + w.y*y.x);
}

// Woodbury + bilinear post-factor for one m (r_ab already include dt)
__device__ __forceinline__ float2 wood(float R0, float I0, float R1, float I1,
                                       float R2, float I2, float R3, float I3,
                                       float t) {
    const float dr = 1.0f + R3, di = I3;
    const float idn = __fdividef(1.0f, dr*dr + di*di);
    const float numr = R1*R2 - I1*I2;
    const float numi = R1*I2 + I1*R2;
    const float cr = (numr*dr + numi*di) * idn;
    const float ci = (numi*dr - numr*di) * idn;
    const float kfr = R0 - cr, kfi = I0 - ci;
    return make_float2(kfr - kfi*t, kfi + kfr*t);   // * (1 + i t)
}

// One m-pair (t0, t1) through the full Cauchy + Woodbury chain.
__device__ __forceinline__ void cauchy_pair(
    const ulonglong2* __restrict__ s_cd,
    const ulonglong2 (*__restrict__ s_ab)[NN2],
    float t0, float t1, float2& o0, float2& o1)
{
    const u64 tp  = pk2(t0, t1);
    const u64 tn  = pk2(-t0, -t1);
    const u64 t2n = pk2(-4.0f*t0*t0, -4.0f*t1*t1);

    u64 aR0=0, aR1=0, aR2=0, aR3=0;     // Re sums
    u64 aJ0=0, aJ1=0, aJ2=0, aJ3=0;     // -Im sums

    #pragma unroll 4
    for (int n = 0; n < NN2; n++) {
        const ulonglong2 cd = s_cd[n];
        const u64 e   = add2(cd.x, t2n);            // c - 4t^2
        const u64 f   = mul2(cd.y, tp);             // d*t
        const u64 mag = fma2(e, e, mul2(f, f));
        float mlo, mhi; upk2(mag, mlo, mhi);
        const u64 r   = pk2(__fdividef(1.0f, mlo), __fdividef(1.0f, mhi));
        const u64 er  = mul2(e, r);
        const u64 fr  = mul2(f, r);
        const u64 tfr  = mul2(tp, fr);
        const u64 nter = mul2(tn, er);              // -t*e*r
        ulonglong2 ab;
        ab = s_ab[0][n];
        aR0 = fma2(ab.x, tfr,  fma2(ab.y, er, aR0));
        aJ0 = fma2(ab.x, nter, fma2(ab.y, fr, aJ0));
        ab = s_ab[1][n];
        aR1 = fma2(ab.x, tfr,  fma2(ab.y, er, aR1));
        aJ1 = fma2(ab.x, nter, fma2(ab.y, fr, aJ1));
        ab = s_ab[2][n];
        aR2 = fma2(ab.x, tfr,  fma2(ab.y, er, aR2));
        aJ2 = fma2(ab.x, nter, fma2(ab.y, fr, aJ2));
        ab = s_ab[3][n];
        aR3 = fma2(ab.x, tfr,  fma2(ab.y, er, aR3));
        aJ3 = fma2(ab.x, nter, fma2(ab.y, fr, aJ3));
    }

    float R0l,R0h,R1l,R1h,R2l,R2h,R3l,R3h;
    float J0l,J0h,J1l,J1h,J2l,J2h,J3l,J3h;
    upk2(aR0,R0l,R0h); upk2(aR1,R1l,R1h); upk2(aR2,R2l,R2h); upk2(aR3,R3l,R3h);
    upk2(aJ0,J0l,J0h); upk2(aJ1,J1l,J1h); upk2(aJ2,J2l,J2h); upk2(aJ3,J3l,J3h);

    o0 = wood(R0l,-J0l, R1l,-J1l, R2l,-J2l, R3l,-J3l, t0);
    o1 = wood(R0h,-J0h, R1h,-J1h, R2h,-J2h, R3h,-J3h, t1);
}

// ---------------------------------------------------------------------------
// Fused kernel: one 256-thread block per h, 4 CTAs/SM -> single wave.
// Phase A: Cauchy + Woodbury spectrum (two sequential m-chunks per thread).
// Phase B: irfft(2048) via real-packing + 1024-pt RADIX-4 Stockham (5 stages).
// ---------------------------------------------------------------------------
__global__ void __launch_bounds__(256, 4)
fused_kernel(const float* __restrict__ log_dt,
             const float* __restrict__ log_w_real,
             const float* __restrict__ w_imag,
             const float* __restrict__ Bmat,
             const float* __restrict__ Cmat,
             const float* __restrict__ Pmat,
             float* __restrict__ out)
{
    __shared__ ulonglong2 s_cd[NN2];        // (c,c),(d,d)
    __shared__ ulonglong2 s_ab[4][NN2];     // (a,a),(b,b) per v-matrix (dt folded)
    __shared__ float2 kfs[MM + 1];          // half-spectrum
    __shared__ float2 sA[1024];
    __shared__ float2 sB[1024];
    __shared__ float2 tw4[768];             // tw4[j] = e^{+2*pi*i*j/1024}

    const int h   = blockIdx.x;
    const int tid = threadIdx.x;

    // twiddle table (3 entries per thread)
    #pragma unroll
    for (int r = 0; r < 3; r++) {
        const int j = tid + r * 256;
        float s, c; sincospif((float)j * (1.0f/512.0f), &s, &c);
        tw4[j] = make_float2(c, s);
    }

    if (tid < NN2) {
        const int n   = tid;
        const int idx = h * NN2 + n;
        const float dt = expf(log_dt[h]);
        const float wr = -expf(log_w_real[idx]) * dt;
        const float wi = w_imag[idx] * dt;
        const float c  = wr*wr + wi*wi;
        const float d  = -4.0f * wr;

        const float Br = Bmat[2*idx], Bi = Bmat[2*idx+1];
        const float Cr = Cmat[2*idx], Ci = Cmat[2*idx+1];
        const float Pr = Pmat[2*idx], Pi = Pmat[2*idx+1];
        float vr[4], vi[4];
        vr[0] = Br*Cr - Bi*Ci;  vi[0] = Br*Ci + Bi*Cr;   // B*C
        vr[1] = Br*Pr + Bi*Pi;  vi[1] = Bi*Pr - Br*Pi;   // B*conj(P)
        vr[2] = Pr*Cr - Pi*Ci;  vi[2] = Pr*Ci + Pi*Cr;   // P*C
        vr[3] = Pr*Pr + Pi*Pi;  vi[3] = 0.0f;            // |P|^2

        s_cd[n] = make_ulonglong2(pk2(c, c), pk2(d, d));
        #pragma unroll
        for (int k = 0; k < 4; k++) {
            const float a =  4.0f * dt * vr[k];
            const float b = -2.0f * dt * (vr[k]*wr + vi[k]*wi);
            s_ab[k][n] = make_ulonglong2(pk2(a, a), pk2(b, b));
        }
    }
    __syncthreads();

    // ================= Phase A: spectrum =================
    #pragma unroll 1
    for (int pass = 0; pass < 2; pass++) {
        const int m0 = 2 * (tid + 256 * pass);
        float s0, c0, s1, c1;
        sincospif((float)m0       * (1.0f/2048.0f), &s0, &c0);
        sincospif((float)(m0 + 1) * (1.0f/2048.0f), &s1, &c1);
        const float t0 = fminf(__fdividef(s0, c0), 1e8f);   // tan(pi m/L)
        const float t1 = fminf(__fdividef(s1, c1), 1e8f);

        float2 o0, o1;
        cauchy_pair(s_cd, s_ab, t0, t1, o0, o1);
        float4* dst = (float4*)&kfs[m0];
        *dst = make_float4(o0.x, o0.y, o1.x, o1.y);
    }
    // Nyquist m=1024 (t clamped -> converged asymptotic limit)
    if (tid == 0) {
        float2 o0, o1;
        cauchy_pair(s_cd, s_ab, 1e8f, 1e8f, o0, o1);
        kfs[1024] = o0;
    }
    __syncthreads();

    // ================= Phase B: irfft =================
    // Z'[m] = (E[m] + i*O[m]) / 1024  (real-packing of the c2r transform)
    #pragma unroll
    for (int r = 0; r < 4; r++) {
        const int m = tid + r * 256;
        float2 km = kfs[m];
        float2 kn = kfs[1024 - m];
        if (m == 0) { km.y = 0.f; kn.y = 0.f; }
        const float Ex = 0.5f * (km.x + kn.x);
        const float Ey = 0.5f * (km.y - kn.y);
        const float Ox = 0.5f * (km.x - kn.x);
        const float Oy = 0.5f * (km.y + kn.y);
        float s, c;
        sincospif((float)m * (1.0f / 1024.0f), &s, &c);
        const float Orx = Ox * c - Oy * s;
        const float Ory = Ox * s + Oy * c;
        const float scale = 1.0f / 1024.0f;
        sA[m] = make_float2((Ex - Ory) * scale, (Ey + Orx) * scale);
    }

    // 5 radix-4 Stockham stages (self-sorting), inverse sign (+).
    // Butterfly: a=x0+x2, b=x0-x2, c=x1+x3, d=x1-x3;
    //   y0=a+c, y1=W^p(b+id), y2=W^{2p}(a-c), y3=W^{3p}(b-id), W=e^{2pi i/ncur}
    float2* src = sA;
    float2* dst = sB;
    int s_ = 1, ls = 0;
    #pragma unroll 1
    for (int ncur = 1024; ncur >= 4; ncur >>= 2) {
        __syncthreads();
        const int mq = ncur >> 2;
        const int q  = tid & (s_ - 1);
        const int p  = tid >> ls;
        const int rb = q + s_ * p;
        const float2 x0 = src[rb];
        const float2 x1 = src[rb + s_ * mq];
        const float2 x2 = src[rb + s_ * 2 * mq];
        const float2 x3 = src[rb + s_ * 3 * mq];

        const float2 va = make_float2(x0.x + x2.x, x0.y + x2.y);
        const float2 vb = make_float2(x0.x - x2.x, x0.y - x2.y);
        const float2 vc = make_float2(x1.x + x3.x, x1.y + x3.y);
        const float2 vd = make_float2(x1.x - x3.x, x1.y - x3.y);

        const float2 y0 = make_float2(va.x + vc.x, va.y + vc.y);
        const float2 y1 = make_float2(vb.x - vd.y, vb.y + vd.x);   // b + i d
        const float2 y2 = make_float2(va.x - vc.x, va.y - vc.y);
        const float2 y3 = make_float2(vb.x + vd.y, vb.y - vd.x);   // b - i d

        const float2 w1 = tw4[(p)     << ls];
        const float2 w2 = tw4[(2 * p) << ls];
        const float2 w3 = tw4[(3 * p) << ls];

        const int wb = q + s_ * 4 * p;
        dst[wb]          = y0;
        dst[wb + s_]     = cmul(w1, y1);
        dst[wb + 2 * s_] = cmul(w2, y2);
        dst[wb + 3 * s_] = cmul(w3, y3);

        float2* t = src; src = dst; dst = t;
        s_ <<= 2; ls += 2;
    }
    __syncthreads();

    // result in src; z[j] = x[2j] + i*x[2j+1] -> out as float4 (2 complex)
    float4* o4 = (float4*)(out + (size_t)h * LEN);
    #pragma unroll
    for (int r = 0; r < 2; r++) {
        const int j = tid + r * 256;
        const float2 z0 = src[2 * j];
        const float2 z1 = src[2 * j + 1];
        o4[j] = make_float4(z0.x, z0.y, z1.x, z1.y);
    }
}

extern "C" void kernel_launch(void* const* d_in, const int* in_sizes, int n_in,
                              void* d_out, int out_size)
{
    const float* log_dt     = (const float*)d_in[0];
    const float* log_w_real = (const float*)d_in[1];
    const float* w_imag     = (const float*)d_in[2];
    const float* Bmat       = (const float*)d_in[3];
    const float* Cmat       = (const float*)d_in[4];
    const float* Pmat       = (const float*)d_in[5];
    float* out = (float*)d_out;

    fused_kernel<<<HDIM, 256>>>(log_dt, log_w_real, w_imag, Bmat, Cmat, Pmat, out);
}